// round 2
// baseline (speedup 1.0000x reference)
#include <cuda_runtime.h>
#include <math.h>

#define NN   14
#define SEQ  24
#define GH   64
#define E0   56
#define NE   70
#define BATCH 32768

// 44 MB intermediate g2 in [node][batch][seq] layout (== output layout)
__device__ float g_mid[(size_t)NN * BATCH * SEQ];

#define WARPS_A 8
// per-warp shared floats
#define PW_SIZE 2256   // xs/h2:336 + h1:896 + g1:896 + attn:126 + pad:2
// block shared float counts
#define SH_FLOATS (3336 + WARPS_A * PW_SIZE)
#define SH_INTS   (2*NE + (NN+1) + NE)   // src,dst, off, ord = 225
#define SH_BYTES  ((SH_FLOATS + SH_INTS) * 4)

__device__ __forceinline__ void edge_softmax(const int* __restrict__ src,
                                             const int* __restrict__ dst,
                                             const int* __restrict__ off,
                                             const int* __restrict__ ord,
                                             const float* as_, const float* ad_,
                                             float* al, float* m, float* ssum, int lane)
{
    // alpha = leaky_relu(as[src] + ad[dst], 0.2)
    for (int e = lane; e < NE; e += 32) {
        float v = as_[src[e]] + ad_[dst[e]];
        al[e] = (v >= 0.f) ? v : 0.2f * v;
    }
    __syncwarp();
    // per-dst max & sum over its CSR slice
    if (lane < NN) {
        int k0 = off[lane], k1 = off[lane + 1];
        float mm = -1e30f;
        for (int k = k0; k < k1; k++) mm = fmaxf(mm, al[ord[k]]);
        float ss = 0.f;
        for (int k = k0; k < k1; k++) ss += __expf(al[ord[k]] - mm);
        m[lane] = mm; ssum[lane] = ss;
    }
    __syncwarp();
    for (int e = lane; e < NE; e += 32) {
        int d = dst[e];
        al[e] = __expf(al[e] - m[d]) / ssum[d];
    }
    __syncwarp();
}

__global__ void __launch_bounds__(32 * WARPS_A)
gat_kernel(const float* __restrict__ x, const int* __restrict__ ei,
           const float* __restrict__ W1, const float* __restrict__ as1,
           const float* __restrict__ ad1, const float* __restrict__ b1,
           const float* __restrict__ W2, const float* __restrict__ as2,
           const float* __restrict__ ad2, const float* __restrict__ b2)
{
    extern __shared__ float sh[];
    float* sW1  = sh;            // 1536
    float* sW2  = sh + 1536;     // 1536
    float* sAs1 = sh + 3072;     // 64
    float* sAd1 = sh + 3136;     // 64
    float* sAs2 = sh + 3200;     // 24
    float* sAd2 = sh + 3224;     // 24
    float* sB1  = sh + 3248;     // 64
    float* sB2  = sh + 3312;     // 24
    int*   sSrc = (int*)(sh + SH_FLOATS);
    int*   sDst = sSrc + NE;
    int*   sOff = sDst + NE;     // NN+1
    int*   sOrd = sOff + (NN + 1);

    const int tid = threadIdx.x;

    for (int i = tid; i < 1536; i += blockDim.x) { sW1[i] = W1[i]; sW2[i] = W2[i]; }
    if (tid < 64) { sAs1[tid] = as1[tid]; sAd1[tid] = ad1[tid]; sB1[tid] = b1[tid]; }
    if (tid < 24) { sAs2[tid] = as2[tid]; sAd2[tid] = ad2[tid]; sB2[tid] = b2[tid]; }
    // edge_index is int32 on device (JAX x64 disabled): [0..55]=src, [56..111]=dst
    if (tid < E0)       { sSrc[tid] = ei[tid]; sDst[tid] = ei[E0 + tid]; }
    else if (tid < NE)  { sSrc[tid] = tid - E0; sDst[tid] = tid - E0; }
    __syncthreads();
    if (tid == 0) {
        int cnt[NN];
        #pragma unroll
        for (int n = 0; n < NN; n++) cnt[n] = 0;
        for (int e = 0; e < NE; e++) cnt[sDst[e]]++;
        int run = 0;
        sOff[0] = 0;
        for (int n = 0; n < NN; n++) { run += cnt[n]; sOff[n + 1] = run; }
        int pos[NN];
        #pragma unroll
        for (int n = 0; n < NN; n++) pos[n] = sOff[n];
        for (int e = 0; e < NE; e++) sOrd[pos[sDst[e]]++] = e;
    }
    __syncthreads();

    const int warp = tid >> 5, lane = tid & 31;
    float* pw  = sh + 3336 + warp * PW_SIZE;
    float* xs  = pw;                 // 336, later reused as h2 [14][24]
    float* h1  = pw + 336;           // 896
    float* g1  = pw + 1232;          // 896
    float* vas = pw + 2128;          // 14
    float* vad = vas + NN;           // 14
    float* val = vad + NN;           // 70
    float* vm  = val + NE;           // 14
    float* vs  = vm + NN;            // 14

    const int b = blockIdx.x * WARPS_A + warp;
    if (b >= BATCH) return;

    // ---- load x[b] slab (contiguous 336 floats): xs[s*14+n] = x[b,s,n] ----
    const float* xb = x + (size_t)b * (SEQ * NN);
    for (int i = lane; i < SEQ * NN; i += 32) xs[i] = xb[i];
    __syncwarp();

    // ---- GAT1 linear: h1[n][f] = sum_s xs[n,s] * W1[s][f]; fused attn dots ----
    float wA[SEQ], wB[SEQ];
    #pragma unroll
    for (int s = 0; s < SEQ; s++) { wA[s] = sW1[s * GH + lane]; wB[s] = sW1[s * GH + 32 + lane]; }
    const float a1L = sAs1[lane], a1H = sAs1[32 + lane];
    const float d1L = sAd1[lane], d1H = sAd1[32 + lane];
    #pragma unroll
    for (int n = 0; n < NN; n++) {
        float acc0 = 0.f, acc1 = 0.f;
        #pragma unroll
        for (int s = 0; s < SEQ; s++) {
            float xv = xs[s * NN + n];
            acc0 += xv * wA[s];
            acc1 += xv * wB[s];
        }
        h1[n * GH + lane] = acc0;
        h1[n * GH + 32 + lane] = acc1;
        float pa = acc0 * a1L + acc1 * a1H;
        float pd = acc0 * d1L + acc1 * d1H;
        #pragma unroll
        for (int o = 16; o > 0; o >>= 1) {
            pa += __shfl_xor_sync(0xffffffffu, pa, o);
            pd += __shfl_xor_sync(0xffffffffu, pd, o);
        }
        if (lane == 0) { vas[n] = pa; vad[n] = pd; }
    }
    __syncwarp();

    edge_softmax(sSrc, sDst, sOff, sOrd, vas, vad, val, vm, vs, lane);

    // ---- GAT1 aggregate (register acc via CSR) + bias + ELU ----
    const float bb0 = sB1[lane], bb1 = sB1[32 + lane];
    #pragma unroll
    for (int n = 0; n < NN; n++) {
        float r0 = 0.f, r1 = 0.f;
        int k0 = sOff[n], k1 = sOff[n + 1];
        for (int k = k0; k < k1; k++) {
            int e = sOrd[k];
            float w = val[e];
            int s_ = sSrc[e];
            r0 += w * h1[s_ * GH + lane];
            r1 += w * h1[s_ * GH + 32 + lane];
        }
        float v0 = r0 + bb0, v1 = r1 + bb1;
        g1[n * GH + lane]      = (v0 > 0.f) ? v0 : (__expf(v0) - 1.f);
        g1[n * GH + 32 + lane] = (v1 > 0.f) ? v1 : (__expf(v1) - 1.f);
    }
    __syncwarp();

    // ---- GAT2 linear: h2[n][o] = sum_f g1[n][f] * W2[f][o] (o = lane<24) ----
    const int o = (lane < SEQ) ? lane : (lane - SEQ);
    float acc[NN];
    #pragma unroll
    for (int n = 0; n < NN; n++) acc[n] = 0.f;
    #pragma unroll
    for (int fc = 0; fc < 4; fc++) {
        float w2r[16];
        #pragma unroll
        for (int j = 0; j < 16; j++) w2r[j] = sW2[(fc * 16 + j) * SEQ + o];
        #pragma unroll
        for (int n = 0; n < NN; n++) {
            float a = acc[n];
            #pragma unroll
            for (int j = 0; j < 16; j++) a += g1[n * GH + fc * 16 + j] * w2r[j];
            acc[n] = a;
        }
    }
    float* h2 = xs;   // reuse (all lanes past their xs reads)
    const float a2 = (lane < SEQ) ? sAs2[o] : 0.f;
    const float d2 = (lane < SEQ) ? sAd2[o] : 0.f;
    __syncwarp();
    #pragma unroll
    for (int n = 0; n < NN; n++) {
        if (lane < SEQ) h2[n * SEQ + lane] = acc[n];
        float pa = acc[n] * a2;
        float pd = acc[n] * d2;
        #pragma unroll
        for (int off = 16; off > 0; off >>= 1) {
            pa += __shfl_xor_sync(0xffffffffu, pa, off);
            pd += __shfl_xor_sync(0xffffffffu, pd, off);
        }
        if (lane == 0) { vas[n] = pa; vad[n] = pd; }
    }
    __syncwarp();

    edge_softmax(sSrc, sDst, sOff, sOrd, vas, vad, val, vm, vs, lane);

    // ---- GAT2 aggregate + bias, store to g_mid[n][b][s] ----
    if (lane < SEQ) {
        const float bb = sB2[lane];
        #pragma unroll
        for (int n = 0; n < NN; n++) {
            float r = 0.f;
            int k0 = sOff[n], k1 = sOff[n + 1];
            for (int k = k0; k < k1; k++) {
                int e = sOrd[k];
                r += val[e] * h2[sSrc[e] * SEQ + lane];
            }
            g_mid[(size_t)n * BATCH * SEQ + (size_t)b * SEQ + lane] = r + bb;
        }
    }
}

#define WARPS_B 8
__global__ void __launch_bounds__(32 * WARPS_B)
mlp_kernel(const float* __restrict__ f1w, const float* __restrict__ f1b,
           const float* __restrict__ f2w, const float* __restrict__ f2b,
           float* __restrict__ out)
{
    __shared__ float s1[SEQ * GH];
    __shared__ float s2[GH * SEQ];
    __shared__ float sb1[GH];
    __shared__ float sb2[SEQ];
    __shared__ float gsh[WARPS_B][SEQ];
    __shared__ float hsh[WARPS_B][GH];

    const int n   = blockIdx.y;
    const int tid = threadIdx.x;
    for (int i = tid; i < SEQ * GH; i += blockDim.x) {
        s1[i] = f1w[(size_t)n * SEQ * GH + i];
        s2[i] = f2w[(size_t)n * GH * SEQ + i];
    }
    if (tid < GH)  sb1[tid] = f1b[n * GH + tid];
    if (tid < SEQ) sb2[tid] = f2b[n * SEQ + tid];
    __syncthreads();

    const int warp = tid >> 5, lane = tid & 31;
    const float* gbase = g_mid + (size_t)n * BATCH * SEQ;
    float* obase = out + (size_t)n * BATCH * SEQ;

    float w1a[SEQ], w1b[SEQ];
    #pragma unroll
    for (int s = 0; s < SEQ; s++) { w1a[s] = s1[s * GH + lane]; w1b[s] = s1[s * GH + 32 + lane]; }
    const float bb0 = sb1[lane], bb1 = sb1[32 + lane];

    for (int b = blockIdx.x * WARPS_B + warp; b < BATCH; b += gridDim.x * WARPS_B) {
        if (lane < SEQ) gsh[warp][lane] = gbase[(size_t)b * SEQ + lane];
        __syncwarp();
        float h0 = bb0, h1v = bb1;
        #pragma unroll
        for (int s = 0; s < SEQ; s++) {
            float g = gsh[warp][s];
            h0  += g * w1a[s];
            h1v += g * w1b[s];
        }
        h0  = fmaxf(h0, 0.f);
        h1v = fmaxf(h1v, 0.f);
        hsh[warp][lane] = h0;
        hsh[warp][32 + lane] = h1v;
        __syncwarp();
        if (lane < SEQ) {
            float a = sb2[lane];
            #pragma unroll
            for (int f = 0; f < GH; f++) a += hsh[warp][f] * s2[f * SEQ + lane];
            obase[(size_t)b * SEQ + lane] = a;
        }
        __syncwarp();
    }
}

extern "C" void kernel_launch(void* const* d_in, const int* in_sizes, int n_in,
                              void* d_out, int out_size)
{
    const float* x   = (const float*)d_in[0];
    const int*   ei  = (const int*)d_in[1];
    const float* W1  = (const float*)d_in[2];
    const float* as1 = (const float*)d_in[3];
    const float* ad1 = (const float*)d_in[4];
    const float* b1  = (const float*)d_in[5];
    const float* W2  = (const float*)d_in[6];
    const float* as2 = (const float*)d_in[7];
    const float* ad2 = (const float*)d_in[8];
    const float* b2  = (const float*)d_in[9];
    const float* f1w = (const float*)d_in[10];
    const float* f1b = (const float*)d_in[11];
    const float* f2w = (const float*)d_in[12];
    const float* f2b = (const float*)d_in[13];
    float* out = (float*)d_out;

    static int smem_configured = 0;
    if (!smem_configured) {
        cudaFuncSetAttribute((const void*)gat_kernel,
                             cudaFuncAttributeMaxDynamicSharedMemorySize, SH_BYTES);
        smem_configured = 1;
    }

    gat_kernel<<<BATCH / WARPS_A, 32 * WARPS_A, SH_BYTES>>>(
        x, ei, W1, as1, ad1, b1, W2, as2, ad2, b2);

    mlp_kernel<<<dim3(256, NN), 32 * WARPS_B>>>(f1w, f1b, f2w, f2b, out);
}

// round 3
// speedup vs baseline: 3.8511x; 3.8511x over previous
#include <cuda_runtime.h>
#include <math.h>

#define NN    14
#define SEQ   24
#define GH    64
#define E0    56
#define NE    70
#define BATCH 32768

// 44 MB intermediate in [node][batch][seq] layout (== output layout)
__device__ float g_mid[(size_t)NN * BATCH * SEQ];

#define WARPS_A 6
// per-warp smem floats: xst[14*28]=392, g1s[14*68]=952, A[14*16]=224, vas[16]+vad[16]=32
#define PW_SIZE 1600
// block-common floats: W1 1536, W2 1536, W1a 24, W1d 24, W2a 64, W2d 64, B1 64, B2 24, cnt 14*17->240
#define BC_SIZE 3576
#define SH_FLOATS (BC_SIZE + WARPS_A * PW_SIZE)
#define SH_BYTES  (SH_FLOATS * 4)

__global__ void __launch_bounds__(32 * WARPS_A)
gat_kernel(const float* __restrict__ x, const int* __restrict__ ei,
           const float* __restrict__ W1, const float* __restrict__ as1,
           const float* __restrict__ ad1, const float* __restrict__ b1,
           const float* __restrict__ W2, const float* __restrict__ as2,
           const float* __restrict__ ad2, const float* __restrict__ b2)
{
    extern __shared__ float sh[];
    float* sW1  = sh;            // 1536: W1[s*64+f]
    float* sW2  = sh + 1536;     // 1536: W2[f*24+o]
    float* sW1a = sh + 3072;     // 24
    float* sW1d = sh + 3096;     // 24
    float* sW2a = sh + 3120;     // 64
    float* sW2d = sh + 3184;     // 64
    float* sB1  = sh + 3248;     // 64
    float* sB2  = sh + 3312;     // 24
    float* sCnt = sh + 3336;     // 14*17 = 238 (pad 240)

    const int tid = threadIdx.x;

    // ---- phase A: bulk loads + zero cnt ----
    for (int i = tid; i < 1536; i += blockDim.x) { sW1[i] = W1[i]; sW2[i] = W2[i]; }
    if (tid < 64) sB1[tid] = b1[tid];
    if (tid < 24) sB2[tid] = b2[tid];
    for (int i = tid; i < 240; i += blockDim.x) sCnt[i] = 0.f;
    __syncthreads();

    // ---- phase B: attention-vector precompute + edge-count matrix ----
    if (tid < 24) {
        float s_ = 0.f, d_ = 0.f;
        #pragma unroll
        for (int f = 0; f < GH; f++) {
            float w = sW1[tid * GH + f];
            s_ += w * as1[f];
            d_ += w * ad1[f];
        }
        sW1a[tid] = s_; sW1d[tid] = d_;
    } else if (tid < 88) {
        int f = tid - 24;
        float s_ = 0.f, d_ = 0.f;
        #pragma unroll
        for (int o = 0; o < SEQ; o++) {
            float w = sW2[f * SEQ + o];
            s_ += w * as2[o];
            d_ += w * ad2[o];
        }
        sW2a[f] = s_; sW2d[f] = d_;
    } else if (tid >= 176) {
        for (int e = tid - 176; e < NE; e += 16) {
            int s_, d_;
            if (e < E0) { s_ = ei[e]; d_ = ei[E0 + e]; }
            else        { s_ = e - E0; d_ = s_; }
            atomicAdd(&sCnt[d_ * 17 + s_], 1.0f);
        }
    }
    __syncthreads();

    const int warp = tid >> 5, lane = tid & 31;
    const int b = blockIdx.x * WARPS_A + warp;
    if (b >= BATCH) return;

    float* pw  = sh + BC_SIZE + warp * PW_SIZE;
    float* xst = pw;            // [14][28]  x transposed
    float* g1s = pw + 392;      // [14][68]  g1, later t
    float* Aw  = pw + 1344;     // [14][16]  attention weights
    float* vas = pw + 1568;     // 16
    float* vad = pw + 1584;     // 16

    // ---- 1. load x[b] (336 contiguous) and transpose to xst[n][s] ----
    const float* xb = x + (size_t)b * (SEQ * NN);
    for (int i = lane; i < SEQ * NN; i += 32) {
        int s_ = i / NN, n_ = i - s_ * NN;
        xst[n_ * 28 + s_] = xb[i];
    }
    __syncwarp();

    // ---- 2. layer-1 attention dots: vas[n]=x_n·(W1 a_src), vad[n]=x_n·(W1 a_dst) ----
    if (lane < NN) {
        float s_ = 0.f, d_ = 0.f;
        #pragma unroll
        for (int j = 0; j < 6; j++) {
            float4 xv = *(const float4*)&xst[lane * 28 + 4 * j];
            float4 wa = *(const float4*)&sW1a[4 * j];
            float4 wd = *(const float4*)&sW1d[4 * j];
            s_ += xv.x * wa.x + xv.y * wa.y + xv.z * wa.z + xv.w * wa.w;
            d_ += xv.x * wd.x + xv.y * wd.y + xv.z * wd.z + xv.w * wd.w;
        }
        vas[lane] = s_; vad[lane] = d_;
    }

    // ---- 3. h1 in registers (outer product over s): lane owns cols f=lane, lane+32 ----
    float h1a[NN], h1b[NN];
    #pragma unroll
    for (int n = 0; n < NN; n++) { h1a[n] = 0.f; h1b[n] = 0.f; }
    #pragma unroll
    for (int s = 0; s < SEQ; s++) {
        float w0 = sW1[s * GH + lane];
        float w1 = sW1[s * GH + 32 + lane];
        #pragma unroll
        for (int n = 0; n < NN; n++) {
            float xv = xst[n * 28 + s];        // broadcast
            h1a[n] += xv * w0;
            h1b[n] += xv * w1;
        }
    }
    __syncwarp();

    // ---- 4. softmax layer 1 -> Aw, vas := 1/sum ----
    if (lane < NN) {
        const float dn = vad[lane];
        float al[NN], mx = -1e30f;
        #pragma unroll
        for (int m = 0; m < NN; m++) {
            float c = sCnt[lane * 17 + m];
            float v = vas[m] + dn;
            v = (v >= 0.f) ? v : 0.2f * v;
            al[m] = v;
            if (c > 0.f) mx = fmaxf(mx, v);
        }
        float ssum = 0.f;
        #pragma unroll
        for (int m = 0; m < NN; m++) {
            float c = sCnt[lane * 17 + m];
            float e = c * __expf(al[m] - mx);
            ssum += e;
            Aw[lane * 16 + m] = e;
        }
        Aw[lane * 16 + 14] = 0.f;
        Aw[lane * 16 + 15] = 0.f;
        vas[lane] = 1.0f / ssum;
    }
    __syncwarp();

    // ---- 5. aggregate layer 1 (registers) + bias + ELU; stash g1 to smem ----
    float g1a[NN], g1b[NN];
    {
        const float bb0 = sB1[lane], bb1 = sB1[32 + lane];
        #pragma unroll
        for (int n = 0; n < NN; n++) {
            float4 A0 = *(const float4*)&Aw[n * 16 + 0];
            float4 A1 = *(const float4*)&Aw[n * 16 + 4];
            float4 A2 = *(const float4*)&Aw[n * 16 + 8];
            float2 A3 = *(const float2*)&Aw[n * 16 + 12];
            float a0 = A0.x*h1a[0] + A0.y*h1a[1] + A0.z*h1a[2] + A0.w*h1a[3]
                     + A1.x*h1a[4] + A1.y*h1a[5] + A1.z*h1a[6] + A1.w*h1a[7]
                     + A2.x*h1a[8] + A2.y*h1a[9] + A2.z*h1a[10]+ A2.w*h1a[11]
                     + A3.x*h1a[12]+ A3.y*h1a[13];
            float a1 = A0.x*h1b[0] + A0.y*h1b[1] + A0.z*h1b[2] + A0.w*h1b[3]
                     + A1.x*h1b[4] + A1.y*h1b[5] + A1.z*h1b[6] + A1.w*h1b[7]
                     + A2.x*h1b[8] + A2.y*h1b[9] + A2.z*h1b[10]+ A2.w*h1b[11]
                     + A3.x*h1b[12]+ A3.y*h1b[13];
            float inv = vas[n];
            float v0 = a0 * inv + bb0;
            float v1 = a1 * inv + bb1;
            v0 = (v0 > 0.f) ? v0 : (__expf(v0) - 1.f);
            v1 = (v1 > 0.f) ? v1 : (__expf(v1) - 1.f);
            g1a[n] = v0; g1b[n] = v1;
            g1s[n * 68 + lane]      = v0;
            g1s[n * 68 + 32 + lane] = v1;
        }
    }
    __syncwarp();

    // ---- 6. layer-2 attention dots: vas[n]=g1_n·(W2 a_src2), vad[n]=g1_n·(W2 a_dst2) ----
    if (lane < NN) {
        float s_ = 0.f, d_ = 0.f;
        #pragma unroll
        for (int j = 0; j < 16; j++) {
            float4 g = *(const float4*)&g1s[lane * 68 + 4 * j];
            float4 wa = *(const float4*)&sW2a[4 * j];
            float4 wd = *(const float4*)&sW2d[4 * j];
            s_ += g.x * wa.x + g.y * wa.y + g.z * wa.z + g.w * wa.w;
            d_ += g.x * wd.x + g.y * wd.y + g.z * wd.z + g.w * wd.w;
        }
        vas[lane] = s_; vad[lane] = d_;
    }
    __syncwarp();

    // ---- 7. softmax layer 2 -> Aw, vas := 1/sum ----
    if (lane < NN) {
        const float dn = vad[lane];
        float al[NN], mx = -1e30f;
        #pragma unroll
        for (int m = 0; m < NN; m++) {
            float c = sCnt[lane * 17 + m];
            float v = vas[m] + dn;
            v = (v >= 0.f) ? v : 0.2f * v;
            al[m] = v;
            if (c > 0.f) mx = fmaxf(mx, v);
        }
        float ssum = 0.f;
        #pragma unroll
        for (int m = 0; m < NN; m++) {
            float c = sCnt[lane * 17 + m];
            float e = c * __expf(al[m] - mx);
            ssum += e;
            Aw[lane * 16 + m] = e;
        }
        Aw[lane * 16 + 14] = 0.f;
        Aw[lane * 16 + 15] = 0.f;
        vas[lane] = 1.0f / ssum;
    }
    __syncwarp();

    // ---- 8. t = A2·g1 (registers), scaled; stash to smem (overwrite g1s) ----
    #pragma unroll
    for (int n = 0; n < NN; n++) {
        float4 A0 = *(const float4*)&Aw[n * 16 + 0];
        float4 A1 = *(const float4*)&Aw[n * 16 + 4];
        float4 A2 = *(const float4*)&Aw[n * 16 + 8];
        float2 A3 = *(const float2*)&Aw[n * 16 + 12];
        float a0 = A0.x*g1a[0] + A0.y*g1a[1] + A0.z*g1a[2] + A0.w*g1a[3]
                 + A1.x*g1a[4] + A1.y*g1a[5] + A1.z*g1a[6] + A1.w*g1a[7]
                 + A2.x*g1a[8] + A2.y*g1a[9] + A2.z*g1a[10]+ A2.w*g1a[11]
                 + A3.x*g1a[12]+ A3.y*g1a[13];
        float a1 = A0.x*g1b[0] + A0.y*g1b[1] + A0.z*g1b[2] + A0.w*g1b[3]
                 + A1.x*g1b[4] + A1.y*g1b[5] + A1.z*g1b[6] + A1.w*g1b[7]
                 + A2.x*g1b[8] + A2.y*g1b[9] + A2.z*g1b[10]+ A2.w*g1b[11]
                 + A3.x*g1b[12]+ A3.y*g1b[13];
        float inv = vas[n];
        g1s[n * 68 + lane]      = a0 * inv;   // t[n][lane]
        g1s[n * 68 + 32 + lane] = a1 * inv;   // t[n][lane+32]
    }
    __syncwarp();

    // ---- 9. g2 = t·W2 + b2 -> g_mid[n][b][o] (o = lane < 24) ----
    {
        const int o = (lane < SEQ) ? lane : 0;
        float acc[NN];
        const float bb2 = sB2[o];
        #pragma unroll
        for (int n = 0; n < NN; n++) acc[n] = bb2;
        #pragma unroll
        for (int c = 0; c < 4; c++) {
            float w2r[16];
            #pragma unroll
            for (int j = 0; j < 16; j++) w2r[j] = sW2[(c * 16 + j) * SEQ + o];
            #pragma unroll
            for (int n = 0; n < NN; n++) {
                float4 t0 = *(const float4*)&g1s[n * 68 + c * 16 + 0];
                float4 t1 = *(const float4*)&g1s[n * 68 + c * 16 + 4];
                float4 t2 = *(const float4*)&g1s[n * 68 + c * 16 + 8];
                float4 t3 = *(const float4*)&g1s[n * 68 + c * 16 + 12];
                acc[n] += t0.x*w2r[0] + t0.y*w2r[1] + t0.z*w2r[2] + t0.w*w2r[3]
                        + t1.x*w2r[4] + t1.y*w2r[5] + t1.z*w2r[6] + t1.w*w2r[7]
                        + t2.x*w2r[8] + t2.y*w2r[9] + t2.z*w2r[10]+ t2.w*w2r[11]
                        + t3.x*w2r[12]+ t3.y*w2r[13]+ t3.z*w2r[14]+ t3.w*w2r[15];
            }
        }
        if (lane < SEQ) {
            #pragma unroll
            for (int n = 0; n < NN; n++)
                g_mid[(size_t)n * BATCH * SEQ + (size_t)b * SEQ + lane] = acc[n];
        }
    }
}

#define WARPS_B 8
__global__ void __launch_bounds__(32 * WARPS_B)
mlp_kernel(const float* __restrict__ f1w, const float* __restrict__ f1b,
           const float* __restrict__ f2w, const float* __restrict__ f2b,
           float* __restrict__ out)
{
    __shared__ float s1[SEQ * GH];
    __shared__ float s2[GH * SEQ];
    __shared__ float sb1[GH];
    __shared__ float sb2[SEQ];
    __shared__ float gsh[WARPS_B][SEQ];
    __shared__ float hsh[WARPS_B][GH];

    const int n   = blockIdx.y;
    const int tid = threadIdx.x;
    for (int i = tid; i < SEQ * GH; i += blockDim.x) {
        s1[i] = f1w[(size_t)n * SEQ * GH + i];
        s2[i] = f2w[(size_t)n * GH * SEQ + i];
    }
    if (tid < GH)  sb1[tid] = f1b[n * GH + tid];
    if (tid < SEQ) sb2[tid] = f2b[n * SEQ + tid];
    __syncthreads();

    const int warp = tid >> 5, lane = tid & 31;
    const float* gbase = g_mid + (size_t)n * BATCH * SEQ;
    float* obase = out + (size_t)n * BATCH * SEQ;

    float w1a[SEQ], w1b[SEQ];
    #pragma unroll
    for (int s = 0; s < SEQ; s++) { w1a[s] = s1[s * GH + lane]; w1b[s] = s1[s * GH + 32 + lane]; }
    const float bb0 = sb1[lane], bb1 = sb1[32 + lane];

    for (int b = blockIdx.x * WARPS_B + warp; b < BATCH; b += gridDim.x * WARPS_B) {
        if (lane < 6)
            ((float4*)gsh[warp])[lane] = ((const float4*)(gbase + (size_t)b * SEQ))[lane];
        __syncwarp();
        float h0 = bb0, h1v = bb1;
        #pragma unroll
        for (int j = 0; j < 6; j++) {
            float4 g = *(const float4*)&gsh[warp][4 * j];
            h0  += g.x * w1a[4*j] + g.y * w1a[4*j+1] + g.z * w1a[4*j+2] + g.w * w1a[4*j+3];
            h1v += g.x * w1b[4*j] + g.y * w1b[4*j+1] + g.z * w1b[4*j+2] + g.w * w1b[4*j+3];
        }
        h0  = fmaxf(h0, 0.f);
        h1v = fmaxf(h1v, 0.f);
        hsh[warp][lane] = h0;
        hsh[warp][32 + lane] = h1v;
        __syncwarp();
        if (lane < SEQ) {
            float a = sb2[lane];
            #pragma unroll
            for (int j = 0; j < 16; j++) {
                float4 h4 = *(const float4*)&hsh[warp][4 * j];
                a += h4.x * s2[(4*j  ) * SEQ + lane]
                   + h4.y * s2[(4*j+1) * SEQ + lane]
                   + h4.z * s2[(4*j+2) * SEQ + lane]
                   + h4.w * s2[(4*j+3) * SEQ + lane];
            }
            obase[(size_t)b * SEQ + lane] = a;
        }
        __syncwarp();
    }
}

extern "C" void kernel_launch(void* const* d_in, const int* in_sizes, int n_in,
                              void* d_out, int out_size)
{
    const float* x   = (const float*)d_in[0];
    const int*   ei  = (const int*)d_in[1];
    const float* W1  = (const float*)d_in[2];
    const float* as1 = (const float*)d_in[3];
    const float* ad1 = (const float*)d_in[4];
    const float* b1  = (const float*)d_in[5];
    const float* W2  = (const float*)d_in[6];
    const float* as2 = (const float*)d_in[7];
    const float* ad2 = (const float*)d_in[8];
    const float* b2  = (const float*)d_in[9];
    const float* f1w = (const float*)d_in[10];
    const float* f1b = (const float*)d_in[11];
    const float* f2w = (const float*)d_in[12];
    const float* f2b = (const float*)d_in[13];
    float* out = (float*)d_out;

    static int smem_configured = 0;
    if (!smem_configured) {
        cudaFuncSetAttribute((const void*)gat_kernel,
                             cudaFuncAttributeMaxDynamicSharedMemorySize, SH_BYTES);
        smem_configured = 1;
    }

    gat_kernel<<<(BATCH + WARPS_A - 1) / WARPS_A, 32 * WARPS_A, SH_BYTES>>>(
        x, ei, W1, as1, ad1, b1, W2, as2, ad2, b2);

    mlp_kernel<<<dim3(256, NN), 32 * WARPS_B>>>(f1w, f1b, f2w, f2b, out);
}

// round 4
// speedup vs baseline: 4.2180x; 1.0953x over previous
#include <cuda_runtime.h>
#include <math.h>

#define NN    14
#define SEQ   24
#define GH    64
#define E0    56
#define NE    70
#define BATCH 32768

// 44 MB intermediate in [node][batch][seq] layout (== output layout)
__device__ float g_mid[(size_t)NN * BATCH * SEQ];

// ---------------- f32x2 packed-math helpers (Blackwell FFMA2) ----------------
typedef unsigned long long u64;

__device__ __forceinline__ u64 pk2(float lo, float hi) {
    u64 r; asm("mov.b64 %0, {%1,%2};" : "=l"(r) : "f"(lo), "f"(hi)); return r;
}
__device__ __forceinline__ void upk2(u64 v, float& lo, float& hi) {
    asm("mov.b64 {%0,%1}, %2;" : "=f"(lo), "=f"(hi) : "l"(v));
}
__device__ __forceinline__ u64 ff2(u64 a, u64 b, u64 c) {   // {a.lo*b.lo+c.lo, a.hi*b.hi+c.hi}
    u64 d; asm("fma.rn.f32x2 %0, %1, %2, %3;" : "=l"(d) : "l"(a), "l"(b), "l"(c)); return d;
}

// ================================ GAT kernel =================================
#define WARPS_A 6
// per-warp floats: buf 952 (xdup[14][24] doubles=672 overlaid by g1s[14][68]=952), Aw 224, vas 16, vad 16
#define PW_SIZE 1208
// block-common floats: W1pair 1536, W2 1536, W1ad 48, W2a 64, W2d 64, B1 64, B2 24, cnt 240
#define BC_SIZE 3576
#define SH_FLOATS (BC_SIZE + WARPS_A * PW_SIZE)
#define SH_BYTES  (SH_FLOATS * 4)

__global__ void __launch_bounds__(32 * WARPS_A)
gat_kernel(const float* __restrict__ x, const int* __restrict__ ei,
           const float* __restrict__ W1, const float* __restrict__ as1,
           const float* __restrict__ ad1, const float* __restrict__ b1,
           const float* __restrict__ W2, const float* __restrict__ as2,
           const float* __restrict__ ad2, const float* __restrict__ b2)
{
    extern __shared__ float sh[];
    u64*   sW1p = (u64*)sh;          // 768 doubles: {W1[s][l], W1[s][l+32]}  (floats 0..1535)
    float* sW2  = sh + 1536;         // 1536: W2[f*24+o]
    u64*   sW1ad= (u64*)(sh + 3072); // 24 doubles: {W1·a_src1, W1·a_dst1}[s] (floats 3072..3119)
    float* sW2a = sh + 3120;         // 64
    float* sW2d = sh + 3184;         // 64
    float* sB1  = sh + 3248;         // 64
    float* sB2  = sh + 3312;         // 24
    float* sCnt = sh + 3336;         // 14*17 = 238 (pad 240)

    const int tid = threadIdx.x;

    // ---- phase A: bulk loads ----
    for (int i = tid; i < 768; i += blockDim.x) {
        int s_ = i >> 5, l = i & 31;
        sW1p[i] = pk2(W1[s_ * GH + l], W1[s_ * GH + 32 + l]);
    }
    for (int i = tid; i < 1536; i += blockDim.x) sW2[i] = W2[i];
    if (tid < 64) sB1[tid] = b1[tid];
    if (tid < 24) sB2[tid] = b2[tid];
    for (int i = tid; i < 240; i += blockDim.x) sCnt[i] = 0.f;
    __syncthreads();

    // ---- phase B: attention-vector precompute + edge-count matrix ----
    if (tid < 24) {
        float s_ = 0.f, d_ = 0.f;
        #pragma unroll
        for (int f = 0; f < GH; f++) {
            float w = W1[tid * GH + f];
            s_ += w * as1[f];
            d_ += w * ad1[f];
        }
        sW1ad[tid] = pk2(s_, d_);
    } else if (tid < 88) {
        int f = tid - 24;
        float s_ = 0.f, d_ = 0.f;
        #pragma unroll
        for (int o = 0; o < SEQ; o++) {
            float w = sW2[f * SEQ + o];
            s_ += w * as2[o];
            d_ += w * ad2[o];
        }
        sW2a[f] = s_; sW2d[f] = d_;
    } else if (tid >= 176) {
        for (int e = tid - 176; e < NE; e += 16) {
            int s_, d_;
            if (e < E0) { s_ = ei[e]; d_ = ei[E0 + e]; }
            else        { s_ = e - E0; d_ = s_; }
            atomicAdd(&sCnt[d_ * 17 + s_], 1.0f);
        }
    }
    __syncthreads();

    const int warp = tid >> 5, lane = tid & 31;
    const int b = blockIdx.x * WARPS_A + warp;
    if (b >= BATCH) return;

    float* pw  = sh + BC_SIZE + warp * PW_SIZE;
    u64*   xu  = (u64*)pw;      // [14][24] duplicated x  (dead after step 3)
    float* g1s = pw;            // [14][68] g1, later t   (overlays xu)
    float* Aw  = pw + 952;      // [14][16]
    float* vas = pw + 1176;     // 16
    float* vad = pw + 1192;     // 16

    // ---- 1. load x[b] (336 contiguous) -> duplicated transposed xu[n][s] = {x,x} ----
    {
        const float4* xb4 = (const float4*)(x + (size_t)b * (SEQ * NN));
        for (int i4 = lane; i4 < 84; i4 += 32) {
            float4 v = xb4[i4];
            int base = i4 * 4;
            int s0 = base / NN,       n0 = base - s0 * NN;
            int s1 = (base+1) / NN,   n1 = (base+1) - s1 * NN;
            int s2_ = (base+2) / NN,  n2 = (base+2) - s2_ * NN;
            int s3 = (base+3) / NN,   n3 = (base+3) - s3 * NN;
            xu[n0 * 24 + s0]  = pk2(v.x, v.x);
            xu[n1 * 24 + s1]  = pk2(v.y, v.y);
            xu[n2 * 24 + s2_] = pk2(v.z, v.z);
            xu[n3 * 24 + s3]  = pk2(v.w, v.w);
        }
    }
    __syncwarp();

    // ---- 2. layer-1 attention dots (packed): {vas,vad}[n] = sum_s {x,x}*{W1a,W1d} ----
    if (lane < NN) {
        u64 acc = 0ull;
        #pragma unroll
        for (int s = 0; s < SEQ; s++) acc = ff2(xu[lane * 24 + s], sW1ad[s], acc);
        float a_, d_; upk2(acc, a_, d_);
        vas[lane] = a_; vad[lane] = d_;
    }

    // ---- 3. h1 packed in registers: h2[n] = {h1[n][lane], h1[n][lane+32]} ----
    u64 h2[NN];
    #pragma unroll
    for (int n = 0; n < NN; n++) h2[n] = 0ull;
    #pragma unroll
    for (int s = 0; s < SEQ; s++) {
        u64 wv = sW1p[s * 32 + lane];
        #pragma unroll
        for (int n = 0; n < NN; n++) h2[n] = ff2(xu[n * 24 + s], wv, h2[n]);
    }
    float h1a[NN], h1b[NN];
    #pragma unroll
    for (int n = 0; n < NN; n++) upk2(h2[n], h1a[n], h1b[n]);
    __syncwarp();

    // ---- 4. softmax layer 1 -> Aw, vas := 1/sum ----
    if (lane < NN) {
        const float dn = vad[lane];
        float al[NN], mx = -1e30f;
        #pragma unroll
        for (int m = 0; m < NN; m++) {
            float c = sCnt[lane * 17 + m];
            float v = vas[m] + dn;
            v = (v >= 0.f) ? v : 0.2f * v;
            al[m] = v;
            if (c > 0.f) mx = fmaxf(mx, v);
        }
        float ssum = 0.f;
        #pragma unroll
        for (int m = 0; m < NN; m++) {
            float c = sCnt[lane * 17 + m];
            float e = c * __expf(al[m] - mx);
            ssum += e;
            Aw[lane * 16 + m] = e;
        }
        Aw[lane * 16 + 14] = 0.f;
        Aw[lane * 16 + 15] = 0.f;
        vas[lane] = 1.0f / ssum;
    }
    __syncwarp();

    // ---- 5. aggregate layer 1 (registers) + bias + ELU; stash g1 to smem ----
    float g1a[NN], g1b[NN];
    {
        const float bb0 = sB1[lane], bb1 = sB1[32 + lane];
        #pragma unroll
        for (int n = 0; n < NN; n++) {
            float4 A0 = *(const float4*)&Aw[n * 16 + 0];
            float4 A1 = *(const float4*)&Aw[n * 16 + 4];
            float4 A2 = *(const float4*)&Aw[n * 16 + 8];
            float2 A3 = *(const float2*)&Aw[n * 16 + 12];
            float a0 = A0.x*h1a[0] + A0.y*h1a[1] + A0.z*h1a[2] + A0.w*h1a[3]
                     + A1.x*h1a[4] + A1.y*h1a[5] + A1.z*h1a[6] + A1.w*h1a[7]
                     + A2.x*h1a[8] + A2.y*h1a[9] + A2.z*h1a[10]+ A2.w*h1a[11]
                     + A3.x*h1a[12]+ A3.y*h1a[13];
            float a1 = A0.x*h1b[0] + A0.y*h1b[1] + A0.z*h1b[2] + A0.w*h1b[3]
                     + A1.x*h1b[4] + A1.y*h1b[5] + A1.z*h1b[6] + A1.w*h1b[7]
                     + A2.x*h1b[8] + A2.y*h1b[9] + A2.z*h1b[10]+ A2.w*h1b[11]
                     + A3.x*h1b[12]+ A3.y*h1b[13];
            float inv = vas[n];
            float v0 = a0 * inv + bb0;
            float v1 = a1 * inv + bb1;
            v0 = (v0 > 0.f) ? v0 : (__expf(v0) - 1.f);
            v1 = (v1 > 0.f) ? v1 : (__expf(v1) - 1.f);
            g1a[n] = v0; g1b[n] = v1;
            g1s[n * 68 + lane]      = v0;
            g1s[n * 68 + 32 + lane] = v1;
        }
    }
    __syncwarp();

    // ---- 6. layer-2 attention dots ----
    if (lane < NN) {
        float s_ = 0.f, d_ = 0.f;
        #pragma unroll
        for (int j = 0; j < 16; j++) {
            float4 g = *(const float4*)&g1s[lane * 68 + 4 * j];
            float4 wa = *(const float4*)&sW2a[4 * j];
            float4 wd = *(const float4*)&sW2d[4 * j];
            s_ += g.x * wa.x + g.y * wa.y + g.z * wa.z + g.w * wa.w;
            d_ += g.x * wd.x + g.y * wd.y + g.z * wd.z + g.w * wd.w;
        }
        vas[lane] = s_; vad[lane] = d_;
    }
    __syncwarp();

    // ---- 7. softmax layer 2 -> Aw, vas := 1/sum ----
    if (lane < NN) {
        const float dn = vad[lane];
        float al[NN], mx = -1e30f;
        #pragma unroll
        for (int m = 0; m < NN; m++) {
            float c = sCnt[lane * 17 + m];
            float v = vas[m] + dn;
            v = (v >= 0.f) ? v : 0.2f * v;
            al[m] = v;
            if (c > 0.f) mx = fmaxf(mx, v);
        }
        float ssum = 0.f;
        #pragma unroll
        for (int m = 0; m < NN; m++) {
            float c = sCnt[lane * 17 + m];
            float e = c * __expf(al[m] - mx);
            ssum += e;
            Aw[lane * 16 + m] = e;
        }
        Aw[lane * 16 + 14] = 0.f;
        Aw[lane * 16 + 15] = 0.f;
        vas[lane] = 1.0f / ssum;
    }
    __syncwarp();

    // ---- 8. t = A2·g1 (registers), scaled; stash to smem (overwrite g1s) ----
    #pragma unroll
    for (int n = 0; n < NN; n++) {
        float4 A0 = *(const float4*)&Aw[n * 16 + 0];
        float4 A1 = *(const float4*)&Aw[n * 16 + 4];
        float4 A2 = *(const float4*)&Aw[n * 16 + 8];
        float2 A3 = *(const float2*)&Aw[n * 16 + 12];
        float a0 = A0.x*g1a[0] + A0.y*g1a[1] + A0.z*g1a[2] + A0.w*g1a[3]
                 + A1.x*g1a[4] + A1.y*g1a[5] + A1.z*g1a[6] + A1.w*g1a[7]
                 + A2.x*g1a[8] + A2.y*g1a[9] + A2.z*g1a[10]+ A2.w*g1a[11]
                 + A3.x*g1a[12]+ A3.y*g1a[13];
        float a1 = A0.x*g1b[0] + A0.y*g1b[1] + A0.z*g1b[2] + A0.w*g1b[3]
                 + A1.x*g1b[4] + A1.y*g1b[5] + A1.z*g1b[6] + A1.w*g1b[7]
                 + A2.x*g1b[8] + A2.y*g1b[9] + A2.z*g1b[10]+ A2.w*g1b[11]
                 + A3.x*g1b[12]+ A3.y*g1b[13];
        float inv = vas[n];
        g1s[n * 68 + lane]      = a0 * inv;
        g1s[n * 68 + 32 + lane] = a1 * inv;
    }
    __syncwarp();

    // ---- 9. g2 = t·W2 + b2 -> g_mid[n][b][o] (o = lane < 24) ----
    {
        const int o = (lane < SEQ) ? lane : 0;
        float acc[NN];
        const float bb2 = sB2[o];
        #pragma unroll
        for (int n = 0; n < NN; n++) acc[n] = bb2;
        #pragma unroll
        for (int c = 0; c < 4; c++) {
            float w2r[16];
            #pragma unroll
            for (int j = 0; j < 16; j++) w2r[j] = sW2[(c * 16 + j) * SEQ + o];
            #pragma unroll
            for (int n = 0; n < NN; n++) {
                float4 t0 = *(const float4*)&g1s[n * 68 + c * 16 + 0];
                float4 t1 = *(const float4*)&g1s[n * 68 + c * 16 + 4];
                float4 t2 = *(const float4*)&g1s[n * 68 + c * 16 + 8];
                float4 t3 = *(const float4*)&g1s[n * 68 + c * 16 + 12];
                acc[n] += t0.x*w2r[0] + t0.y*w2r[1] + t0.z*w2r[2] + t0.w*w2r[3]
                        + t1.x*w2r[4] + t1.y*w2r[5] + t1.z*w2r[6] + t1.w*w2r[7]
                        + t2.x*w2r[8] + t2.y*w2r[9] + t2.z*w2r[10]+ t2.w*w2r[11]
                        + t3.x*w2r[12]+ t3.y*w2r[13]+ t3.z*w2r[14]+ t3.w*w2r[15];
            }
        }
        if (lane < SEQ) {
            #pragma unroll
            for (int n = 0; n < NN; n++)
                g_mid[(size_t)n * BATCH * SEQ + (size_t)b * SEQ + lane] = acc[n];
        }
    }
}

// ================================ MLP kernel =================================
#define WB 4
__global__ void __launch_bounds__(32 * WB)
mlp_kernel(const float* __restrict__ f1w, const float* __restrict__ f1b,
           const float* __restrict__ f2w, const float* __restrict__ f2b,
           float* __restrict__ out)
{
    __shared__ double hshd[WB][32];      // 64 floats per warp, f-contiguous
    __shared__ float  gsh[WB][28];

    const int n    = blockIdx.y;
    const int tid  = threadIdx.x;
    const int warp = tid >> 5, lane = tid & 31;
    const int o    = (lane < SEQ) ? lane : lane - SEQ;

    // ---- register-cache weights: W1 columns (lane, lane+32), W2 column o (packed pairs) ----
    const float* w1base = f1w + (size_t)n * SEQ * GH;
    float w1a[SEQ], w1b[SEQ];
    #pragma unroll
    for (int s = 0; s < SEQ; s++) {
        w1a[s] = w1base[s * GH + lane];
        w1b[s] = w1base[s * GH + 32 + lane];
    }
    const float* w2base = f2w + (size_t)n * GH * SEQ;
    u64 w2p[GH / 2];
    #pragma unroll
    for (int k = 0; k < GH / 2; k++)
        w2p[k] = pk2(w2base[(2 * k) * SEQ + o], w2base[(2 * k + 1) * SEQ + o]);

    const float bb0   = f1b[n * GH + lane];
    const float bb1   = f1b[n * GH + 32 + lane];
    const float bias2 = f2b[n * SEQ + o];

    const float* gbase = g_mid + (size_t)n * BATCH * SEQ;
    float* obase = out + (size_t)n * BATCH * SEQ;

    for (int b = blockIdx.x * WB + warp; b < BATCH; b += gridDim.x * WB) {
        if (lane < 6)
            ((float4*)gsh[warp])[lane] = ((const float4*)(gbase + (size_t)b * SEQ))[lane];
        __syncwarp();

        // phase 1: h = relu(g·W1 + b1), two outputs per lane, 4 fma chains
        float p0 = bb0, q0 = 0.f, p1 = bb1, q1 = 0.f;
        #pragma unroll
        for (int j = 0; j < 6; j++) {
            float4 g = *(const float4*)&gsh[warp][4 * j];
            p0 = fmaf(g.x, w1a[4*j  ], p0); q0 = fmaf(g.y, w1a[4*j+1], q0);
            p0 = fmaf(g.z, w1a[4*j+2], p0); q0 = fmaf(g.w, w1a[4*j+3], q0);
            p1 = fmaf(g.x, w1b[4*j  ], p1); q1 = fmaf(g.y, w1b[4*j+1], q1);
            p1 = fmaf(g.z, w1b[4*j+2], p1); q1 = fmaf(g.w, w1b[4*j+3], q1);
        }
        float h0  = fmaxf(p0 + q0, 0.f);
        float h1v = fmaxf(p1 + q1, 0.f);
        float* hw = (float*)hshd[warp];
        hw[lane]      = h0;
        hw[32 + lane] = h1v;
        __syncwarp();

        // phase 2: out[o] = h·W2[:,o] + b2, packed FFMA2, 2 chains
        const u64* hu = (const u64*)hshd[warp];
        u64 a0 = 0ull, a1 = 0ull;
        #pragma unroll
        for (int k = 0; k < 16; k++) {
            a0 = ff2(hu[k],      w2p[k],      a0);
            a1 = ff2(hu[k + 16], w2p[k + 16], a1);
        }
        float r0, r1, r2, r3;
        upk2(a0, r0, r1);
        upk2(a1, r2, r3);
        if (lane < SEQ)
            obase[(size_t)b * SEQ + lane] = (r0 + r1) + (r2 + r3) + bias2;
        // next iteration's gsh/hshd writes are ordered by the two syncwarps above
    }
}

extern "C" void kernel_launch(void* const* d_in, const int* in_sizes, int n_in,
                              void* d_out, int out_size)
{
    const float* x   = (const float*)d_in[0];
    const int*   ei  = (const int*)d_in[1];
    const float* W1  = (const float*)d_in[2];
    const float* as1 = (const float*)d_in[3];
    const float* ad1 = (const float*)d_in[4];
    const float* b1  = (const float*)d_in[5];
    const float* W2  = (const float*)d_in[6];
    const float* as2 = (const float*)d_in[7];
    const float* ad2 = (const float*)d_in[8];
    const float* b2  = (const float*)d_in[9];
    const float* f1w = (const float*)d_in[10];
    const float* f1b = (const float*)d_in[11];
    const float* f2w = (const float*)d_in[12];
    const float* f2b = (const float*)d_in[13];
    float* out = (float*)d_out;

    // dynamic smem = 43,296 B < 48 KB default -> no opt-in needed
    gat_kernel<<<(BATCH + WARPS_A - 1) / WARPS_A, 32 * WARPS_A, SH_BYTES>>>(
        x, ei, W1, as1, ad1, b1, W2, as2, ad2, b2);

    mlp_kernel<<<dim3(128, NN), 32 * WB>>>(f1w, f1b, f2w, f2b, out);
}